// round 16
// baseline (speedup 1.0000x reference)
#include <cuda_runtime.h>
#include <cuda_bf16.h>
#include <math.h>
#include <float.h>

#define NN 50000
#define NE 800000
#define DD 128
#define BIGF 1000000000.0f

#define PREP_BLOCKS 12532          // (NN*64 + 128*64) / 256 exactly
#define HIST_BLOCKS 782            // ceil((NE/4)/256)

// ---------------- scratch (static device globals; no allocs) ----------------
__device__ float    g_z[NN * DD];       // z = h@W + b   (25.6 MB)
__device__ float    g_s[NN];            // z . w_src
__device__ float    g_t[NN];            // z . w_dst
__device__ float    g_hnew[NN * DD];    // aggregated output (25.6 MB)
__device__ float    g_colsum[DD];
__device__ float    g_colsq[DD];
__device__ int      g_cnt[NN];          // degree counts
__device__ int      g_off[NN + 1];      // CSR offsets
__device__ int      g_cursor[NN];       // fill cursors
__device__ int2     g_pack[NE];         // per CSR slot: {src, sigma(bits)}
__device__ unsigned g_hh[NN * 64];      // H hi bf16x2 words
__device__ unsigned g_hl[NN * 64];      // H lo bf16x2 words
__device__ unsigned g_wh[128 * 64];     // W^T hi: [col][kpair]
__device__ unsigned g_wl[128 * 64];     // W^T lo

__device__ __forceinline__ float clamp_inf(float v) {
    return isinf(v) ? BIGF : v;
}
__device__ __forceinline__ unsigned short bfb(float x) {
    __nv_bfloat16 b = __float2bfloat16(x);
    return *reinterpret_cast<unsigned short*>(&b);
}
__device__ __forceinline__ float bff(unsigned short u) {
    return __bfloat162float(*reinterpret_cast<__nv_bfloat16*>(&u));
}
__device__ __forceinline__ void pack_hl(float x0, float x1, unsigned& hi, unsigned& lo) {
    unsigned short h0 = bfb(x0);
    unsigned short h1 = bfb(x1);
    float r0 = x0 - bff(h0);
    float r1 = x1 - bff(h1);
    hi = ((unsigned)h1 << 16) | (unsigned)h0;
    lo = ((unsigned)bfb(r1) << 16) | (unsigned)bfb(r0);
}
__device__ __forceinline__ void mma_bf16(float* c, const unsigned* a, unsigned b0, unsigned b1) {
    asm volatile("mma.sync.aligned.m16n8k16.row.col.f32.bf16.bf16.f32 "
                 "{%0,%1,%2,%3}, {%4,%5,%6,%7}, {%8,%9}, {%0,%1,%2,%3};"
                 : "+f"(c[0]), "+f"(c[1]), "+f"(c[2]), "+f"(c[3])
                 : "r"(a[0]), "r"(a[1]), "r"(a[2]), "r"(a[3]), "r"(b0), "r"(b1));
}
__device__ __forceinline__ void ldsm4(unsigned* r, unsigned addr) {
    asm volatile("ldmatrix.sync.aligned.m8n8.x4.shared.b16 {%0,%1,%2,%3}, [%4];"
                 : "=r"(r[0]), "=r"(r[1]), "=r"(r[2]), "=r"(r[3]) : "r"(addr));
}

// ---------------- launch 1: prep (H/W bf16 split) UNION degree histogram ----------------
__global__ void k_pre(const float* __restrict__ H, const float* __restrict__ W,
                      const int* __restrict__ dst) {
    if (blockIdx.x < PREP_BLOCKS) {
        int i = blockIdx.x * blockDim.x + threadIdx.x;
        if (i < NN * 64) {
            float2 v = *(const float2*)&H[i * 2];
            unsigned hi, lo;
            pack_hl(v.x, v.y, hi, lo);
            g_hh[i] = hi;
            g_hl[i] = lo;
        } else {
            int w = i - NN * 64;               // exact grid: i < NN*64 + 8192
            int col = w >> 6;
            int kp = w & 63;
            float x0 = W[(2 * kp) * 128 + col];
            float x1 = W[(2 * kp + 1) * 128 + col];
            unsigned hi, lo;
            pack_hl(x0, x1, hi, lo);
            g_wh[w] = hi;
            g_wl[w] = lo;
        }
    } else {
        int i = ((blockIdx.x - PREP_BLOCKS) * blockDim.x + threadIdx.x) * 4;
        if (i < NE) {
            int4 d4 = *(const int4*)&dst[i];
            atomicAdd(&g_cnt[d4.x], 1);
            atomicAdd(&g_cnt[d4.y], 1);
            atomicAdd(&g_cnt[d4.z], 1);
            atomicAdd(&g_cnt[d4.w], 1);
        }
    }
}

// ---------------- launch 2: exclusive scan (single block) ----------------
__global__ __launch_bounds__(1024) void k_scan() {
    __shared__ int sums[1024];
    const int t = threadIdx.x;
    const int C = (NN + 1023) / 1024;
    int b = t * C;
    int e = min(b + C, NN);
    int s = 0;
    for (int i = b; i < e; i++) s += g_cnt[i];
    sums[t] = s;
    __syncthreads();
    for (int off = 1; off < 1024; off <<= 1) {
        int v = (t >= off) ? sums[t - off] : 0;
        __syncthreads();
        sums[t] += v;
        __syncthreads();
    }
    int running = sums[t] - s;
    for (int i = b; i < e; i++) {
        g_off[i] = running;
        g_cursor[i] = running;
        running += g_cnt[i];
    }
    if (t == 1023) g_off[NN] = NE;
}

// ---------------- launch 3: bf16x3 tensor GEMM + fused attn dots (LDSM fragments) ----------------
#define NKP 12
__global__ __launch_bounds__(256) void k_gemm_bf(const float* __restrict__ Bv,
                                                 const float* __restrict__ AW) {
    __shared__ __align__(16) unsigned Ah[128 * NKP], Al[128 * NKP];
    __shared__ __align__(16) unsigned Bh[128 * NKP], Bl[128 * NKP];
    __shared__ float s_sp[128][2], s_tp[128][2];

    const int tid = threadIdx.x;
    const int lane = tid & 31;
    const int wid = tid >> 5;
    const int g = lane >> 2;
    const int t = lane & 3;
    const int wr = wid & 3;
    const int wc = wid >> 2;
    const int row0 = blockIdx.x * 128;

    const unsigned saAh = (unsigned)__cvta_generic_to_shared(&Ah[0]);
    const unsigned saAl = (unsigned)__cvta_generic_to_shared(&Al[0]);
    const unsigned saBh = (unsigned)__cvta_generic_to_shared(&Bh[0]);
    const unsigned saBl = (unsigned)__cvta_generic_to_shared(&Bl[0]);

    const int rselA = lane & 15;
    const int hselA = lane >> 4;
    const int cselB = (lane & 7) + ((lane >> 4) * 8);
    const int khB = (lane >> 3) & 1;

    float c[2][8][4];
#pragma unroll
    for (int mt = 0; mt < 2; mt++)
#pragma unroll
        for (int nt = 0; nt < 8; nt++)
#pragma unroll
            for (int i = 0; i < 4; i++) c[mt][nt][i] = 0.0f;

    for (int kc = 0; kc < 64; kc += 8) {
        __syncthreads();
#pragma unroll
        for (int l = 0; l < 4; l++) {
            int i = tid + l * 256;
            int row = i >> 3;
            int kp = i & 7;
            int gr = row0 + row;
            unsigned hv = 0, lv = 0;
            if (gr < NN) {
                hv = g_hh[gr * 64 + kc + kp];
                lv = g_hl[gr * 64 + kc + kp];
            }
            Ah[row * NKP + kp] = hv;
            Al[row * NKP + kp] = lv;
        }
#pragma unroll
        for (int l = 0; l < 4; l++) {
            int i = tid + l * 256;
            int col = i >> 3;
            int kp = i & 7;
            Bh[col * NKP + kp] = g_wh[col * 64 + kc + kp];
            Bl[col * NKP + kp] = g_wl[col * 64 + kc + kp];
        }
        __syncthreads();

        unsigned ah[2][4], alr[2][4];
#pragma unroll
        for (int mt = 0; mt < 2; mt++) {
            unsigned off = ((unsigned)((wr * 32 + mt * 16 + rselA) * NKP + hselA * 4)) * 4u;
            ldsm4(ah[mt], saAh + off);
            ldsm4(alr[mt], saAl + off);
        }
#pragma unroll
        for (int ntp = 0; ntp < 4; ntp++) {
            unsigned boff = ((unsigned)((wc * 64 + ntp * 16 + cselB) * NKP + khB * 4)) * 4u;
            unsigned bh4[4], bl4[4];
            ldsm4(bh4, saBh + boff);
            ldsm4(bl4, saBl + boff);
#pragma unroll
            for (int sub = 0; sub < 2; sub++) {
                int nt = ntp * 2 + sub;
                unsigned b0h = bh4[sub * 2], b1h = bh4[sub * 2 + 1];
                unsigned b0l = bl4[sub * 2], b1l = bl4[sub * 2 + 1];
#pragma unroll
                for (int mt = 0; mt < 2; mt++) {
                    mma_bf16(c[mt][nt], ah[mt], b0h, b1h);    // hi*hi
                    mma_bf16(c[mt][nt], alr[mt], b0h, b1h);   // lo*hi
                    mma_bf16(c[mt][nt], ah[mt], b0l, b1l);    // hi*lo
                }
            }
        }
    }

    float sp0[2] = {0.f, 0.f}, tp0[2] = {0.f, 0.f};
    float sp1[2] = {0.f, 0.f}, tp1[2] = {0.f, 0.f};
#pragma unroll
    for (int mt = 0; mt < 2; mt++) {
        int rl0 = wr * 32 + mt * 16 + g;
        int gr0 = row0 + rl0, gr1 = gr0 + 8;
#pragma unroll
        for (int nt = 0; nt < 8; nt++) {
            int col = wc * 64 + nt * 8 + t * 2;
            float2 bb = *(const float2*)&Bv[col];
            float2 ws2 = *(const float2*)&AW[col];
            float2 wd2 = *(const float2*)&AW[128 + col];
            float v0 = clamp_inf(c[mt][nt][0] + bb.x);
            float v1 = clamp_inf(c[mt][nt][1] + bb.y);
            float v2 = clamp_inf(c[mt][nt][2] + bb.x);
            float v3 = clamp_inf(c[mt][nt][3] + bb.y);
            if (gr0 < NN) *(float2*)&g_z[gr0 * 128 + col] = make_float2(v0, v1);
            if (gr1 < NN) *(float2*)&g_z[gr1 * 128 + col] = make_float2(v2, v3);
            sp0[mt] += v0 * ws2.x + v1 * ws2.y;
            tp0[mt] += v0 * wd2.x + v1 * wd2.y;
            sp1[mt] += v2 * ws2.x + v3 * ws2.y;
            tp1[mt] += v2 * wd2.x + v3 * wd2.y;
        }
    }
#pragma unroll
    for (int o = 1; o <= 2; o <<= 1) {
#pragma unroll
        for (int mt = 0; mt < 2; mt++) {
            sp0[mt] += __shfl_xor_sync(0xffffffffu, sp0[mt], o);
            tp0[mt] += __shfl_xor_sync(0xffffffffu, tp0[mt], o);
            sp1[mt] += __shfl_xor_sync(0xffffffffu, sp1[mt], o);
            tp1[mt] += __shfl_xor_sync(0xffffffffu, tp1[mt], o);
        }
    }
    if (t == 0) {
#pragma unroll
        for (int mt = 0; mt < 2; mt++) {
            int rl = wr * 32 + mt * 16 + g;
            s_sp[rl][wc] = sp0[mt];      s_tp[rl][wc] = tp0[mt];
            s_sp[rl + 8][wc] = sp1[mt];  s_tp[rl + 8][wc] = tp1[mt];
        }
    }
    __syncthreads();
    if (tid < 128) {
        int gr = row0 + tid;
        if (gr < NN) {
            g_s[gr] = s_sp[tid][0] + s_sp[tid][1];
            g_t[gr] = s_tp[tid][0] + s_tp[tid][1];
        }
    }
}

// ---------------- launch 4: thin CSR fill + re-zero counters for next replay ----------------
__global__ void k_fill(const int* __restrict__ src, const int* __restrict__ dst,
                       const float* __restrict__ sigma) {
    int gt = blockIdx.x * blockDim.x + threadIdx.x;
    int i = gt * 4;
    if (i < NE) {
        int4 s4 = *(const int4*)&src[i];
        int4 d4 = *(const int4*)&dst[i];
        float4 g4 = *(const float4*)&sigma[i];
        int p;
        p = atomicAdd(&g_cursor[d4.x], 1); g_pack[p] = make_int2(s4.x, __float_as_int(g4.x));
        p = atomicAdd(&g_cursor[d4.y], 1); g_pack[p] = make_int2(s4.y, __float_as_int(g4.y));
        p = atomicAdd(&g_cursor[d4.z], 1); g_pack[p] = make_int2(s4.z, __float_as_int(g4.z));
        p = atomicAdd(&g_cursor[d4.w], 1); g_pack[p] = make_int2(s4.w, __float_as_int(g4.w));
    }
    if (gt < NN) g_cnt[gt] = 0;                          // for next replay
    if (gt < DD) { g_colsum[gt] = 0.0f; g_colsq[gt] = 0.0f; }
}

// ---------------- launch 5: 2 warps per node (column-split), branchless online softmax ----------------
// block = 256 threads = 8 warps = 4 nodes; warp handles 64 columns (float2 per lane).
__global__ __launch_bounds__(256) void k_node(const float* __restrict__ attnb) {
    __shared__ float s_sum[DD];
    __shared__ float s_sq[DD];
    const int tid = threadIdx.x;
    if (tid < DD) { s_sum[tid] = 0.0f; s_sq[tid] = 0.0f; }
    __syncthreads();

    const int lane = tid & 31;
    const int wid = tid >> 5;
    const int node = blockIdx.x * 4 + (wid >> 1);   // NN = 12500*4 exactly
    const int half = wid & 1;
    const int co = half * 64 + lane * 2;            // this warp-lane's 2 columns

    const int beg = g_off[node];
    const int end = g_off[node + 1];
    const float tb = g_t[node] + attnb[0];

    float m = -FLT_MAX, den = 0.0f, bsum = 0.0f;
    float2 a0 = make_float2(0.f, 0.f);
    float2 a1 = make_float2(0.f, 0.f);
    float2 a2 = make_float2(0.f, 0.f);
    float2 a3 = make_float2(0.f, 0.f);

    int j = beg;
    for (; j + 3 < end; j += 4) {
        int2 p0 = g_pack[j],     p1 = g_pack[j + 1];
        int2 p2 = g_pack[j + 2], p3 = g_pack[j + 3];
        float2 z0 = *(const float2*)&g_z[p0.x * DD + co];
        float2 z1 = *(const float2*)&g_z[p1.x * DD + co];
        float2 z2 = *(const float2*)&g_z[p2.x * DD + co];
        float2 z3 = *(const float2*)&g_z[p3.x * DD + co];
        float aa, e0, e1, e2, e3;
        aa = clamp_inf(g_s[p0.x] + tb); e0 = (aa > 0.f) ? aa : 0.01f * aa;
        aa = clamp_inf(g_s[p1.x] + tb); e1 = (aa > 0.f) ? aa : 0.01f * aa;
        aa = clamp_inf(g_s[p2.x] + tb); e2 = (aa > 0.f) ? aa : 0.01f * aa;
        aa = clamp_inf(g_s[p3.x] + tb); e3 = (aa > 0.f) ? aa : 0.01f * aa;
        float l4 = fmaxf(fmaxf(e0, e1), fmaxf(e2, e3));
        float mn = fmaxf(m, l4);
        float f = __expf(m - mn);
        m = mn;
        den *= f;
        a0.x *= f; a0.y *= f;
        a1.x *= f; a1.y *= f;
        a2.x *= f; a2.y *= f;
        a3.x *= f; a3.y *= f;
        float w0 = __expf(e0 - m), w1 = __expf(e1 - m);
        float w2 = __expf(e2 - m), w3 = __expf(e3 - m);
        den += (w0 + w1) + (w2 + w3);
        float s0 = __int_as_float(p0.y), s1 = __int_as_float(p1.y);
        float s2 = __int_as_float(p2.y), s3 = __int_as_float(p3.y);
        bsum += (s0 + s1) + (s2 + s3);
        float c0 = w0 * s0, c1 = w1 * s1, c2 = w2 * s2, c3 = w3 * s3;
        a0.x += c0 * z0.x; a0.y += c0 * z0.y;
        a1.x += c1 * z1.x; a1.y += c1 * z1.y;
        a2.x += c2 * z2.x; a2.y += c2 * z2.y;
        a3.x += c3 * z3.x; a3.y += c3 * z3.y;
    }
    for (; j < end; j++) {
        int2 p0 = g_pack[j];
        float2 z0 = *(const float2*)&g_z[p0.x * DD + co];
        float aa = clamp_inf(g_s[p0.x] + tb);
        float e0 = (aa > 0.f) ? aa : 0.01f * aa;
        float mn = fmaxf(m, e0);
        float f = __expf(m - mn);
        m = mn;
        den *= f;
        a0.x *= f; a0.y *= f;
        a1.x *= f; a1.y *= f;
        a2.x *= f; a2.y *= f;
        a3.x *= f; a3.y *= f;
        float w0 = __expf(e0 - m);
        den += w0;
        float s0 = __int_as_float(p0.y);
        bsum += s0;
        float c0 = w0 * s0;
        a0.x += c0 * z0.x; a0.y += c0 * z0.y;
    }

    float rc = (den > 0.0f) ? (1.0f / den) * (1.0f / (bsum + 1e-6f)) : 0.0f;
    float2 v;
    v.x = clamp_inf(((a0.x + a1.x) + (a2.x + a3.x)) * rc);
    v.y = clamp_inf(((a0.y + a1.y) + (a2.y + a3.y)) * rc);
    *(float2*)&g_hnew[node * DD + co] = v;

    atomicAdd(&s_sum[co + 0], v.x); atomicAdd(&s_sq[co + 0], v.x * v.x);
    atomicAdd(&s_sum[co + 1], v.y); atomicAdd(&s_sq[co + 1], v.y * v.y);

    __syncthreads();
    if (tid < DD) {
        atomicAdd(&g_colsum[tid], s_sum[tid]);
        atomicAdd(&g_colsq[tid], s_sq[tid]);
    }
}

// ---------------- launch 6: batchnorm + elu (vectorized) ----------------
__global__ void k_bn(float* __restrict__ out, const float* __restrict__ gamma,
                     const float* __restrict__ beta) {
    int i = blockIdx.x * blockDim.x + threadIdx.x;   // float4 index
    if (i >= NN * DD / 4) return;
    int c = (i & 31) * 4;
    const float inv_n = 1.0f / (float)NN;
    float4 cs = *(float4*)&g_colsum[c];
    float4 cq = *(float4*)&g_colsq[c];
    float4 gm = *(const float4*)&gamma[c];
    float4 bt = *(const float4*)&beta[c];
    float4 hv = *(float4*)&g_hnew[i * 4];
    float mu, var, xb;
    float4 o;
    mu = cs.x * inv_n; var = cq.x * inv_n - mu * mu;
    xb = (hv.x - mu) * rsqrtf(var + 1e-5f) * gm.x + bt.x;
    o.x = (xb > 0.0f) ? xb : expm1f(xb);
    mu = cs.y * inv_n; var = cq.y * inv_n - mu * mu;
    xb = (hv.y - mu) * rsqrtf(var + 1e-5f) * gm.y + bt.y;
    o.y = (xb > 0.0f) ? xb : expm1f(xb);
    mu = cs.z * inv_n; var = cq.z * inv_n - mu * mu;
    xb = (hv.z - mu) * rsqrtf(var + 1e-5f) * gm.z + bt.z;
    o.z = (xb > 0.0f) ? xb : expm1f(xb);
    mu = cs.w * inv_n; var = cq.w * inv_n - mu * mu;
    xb = (hv.w - mu) * rsqrtf(var + 1e-5f) * gm.w + bt.w;
    o.w = (xb > 0.0f) ? xb : expm1f(xb);
    *(float4*)&out[i * 4] = o;
}

// ---------------- launcher: 6 serial launches, no side stream, no events ----------------
extern "C" void kernel_launch(void* const* d_in, const int* in_sizes, int n_in,
                              void* d_out, int out_size) {
    const float* h     = (const float*)d_in[0];
    const int*   src   = (const int*)d_in[1];
    const int*   dst   = (const int*)d_in[2];
    const float* sigma = (const float*)d_in[3];
    const float* fcw   = (const float*)d_in[4];
    const float* fcb   = (const float*)d_in[5];
    const float* attnw = (const float*)d_in[6];
    const float* attnb = (const float*)d_in[7];
    const float* gamma = (const float*)d_in[8];
    const float* beta  = (const float*)d_in[9];
    float* out = (float*)d_out;

    k_pre<<<PREP_BLOCKS + HIST_BLOCKS, 256>>>(h, fcw, dst);        // 1
    k_scan<<<1, 1024>>>();                                         // 2
    k_gemm_bf<<<(NN + 127) / 128, 256>>>(fcb, attnw);              // 3
    k_fill<<<(NE / 4 + 255) / 256, 256>>>(src, dst, sigma);        // 4  <-- profiled
    k_node<<<NN / 4, 256>>>(attnb);                                // 5
    k_bn<<<(NN * DD / 4 + 255) / 256, 256>>>(out, gamma, beta);    // 6
}

// round 17
// speedup vs baseline: 1.3925x; 1.3925x over previous
#include <cuda_runtime.h>
#include <cuda_bf16.h>
#include <math.h>
#include <float.h>

#define NN 50000
#define NE 800000
#define DD 128
#define BIGF 1000000000.0f

// ---------------- scratch (static device globals; no allocs) ----------------
__device__ float    g_z[NN * DD];       // z = h@W + b   (25.6 MB)
__device__ float    g_s[NN];            // z . w_src
__device__ float    g_t[NN];            // z . w_dst
__device__ float    g_hnew[NN * DD];    // aggregated output (25.6 MB)
__device__ float    g_colsum[DD];
__device__ float    g_colsq[DD];
__device__ int      g_cnt[NN];          // degree counts
__device__ int      g_off[NN + 1];      // CSR offsets
__device__ int      g_cursor[NN];       // fill cursors
__device__ int2     g_pack[NE];         // per CSR slot: {src, sigma(bits)}
__device__ unsigned g_hh[NN * 64];      // H hi bf16x2 words
__device__ unsigned g_hl[NN * 64];      // H lo bf16x2 words
__device__ unsigned g_wh[128 * 64];     // W^T hi: [col][kpair]
__device__ unsigned g_wl[128 * 64];     // W^T lo

__device__ __forceinline__ float clamp_inf(float v) {
    return isinf(v) ? BIGF : v;
}
__device__ __forceinline__ unsigned short bfb(float x) {
    __nv_bfloat16 b = __float2bfloat16(x);
    return *reinterpret_cast<unsigned short*>(&b);
}
__device__ __forceinline__ float bff(unsigned short u) {
    return __bfloat162float(*reinterpret_cast<__nv_bfloat16*>(&u));
}
__device__ __forceinline__ void pack_hl(float x0, float x1, unsigned& hi, unsigned& lo) {
    unsigned short h0 = bfb(x0);
    unsigned short h1 = bfb(x1);
    float r0 = x0 - bff(h0);
    float r1 = x1 - bff(h1);
    hi = ((unsigned)h1 << 16) | (unsigned)h0;
    lo = ((unsigned)bfb(r1) << 16) | (unsigned)bfb(r0);
}
__device__ __forceinline__ void mma_bf16(float* c, const unsigned* a, unsigned b0, unsigned b1) {
    asm volatile("mma.sync.aligned.m16n8k16.row.col.f32.bf16.bf16.f32 "
                 "{%0,%1,%2,%3}, {%4,%5,%6,%7}, {%8,%9}, {%0,%1,%2,%3};"
                 : "+f"(c[0]), "+f"(c[1]), "+f"(c[2]), "+f"(c[3])
                 : "r"(a[0]), "r"(a[1]), "r"(a[2]), "r"(a[3]), "r"(b0), "r"(b1));
}
__device__ __forceinline__ void ldsm4(unsigned* r, unsigned addr) {
    asm volatile("ldmatrix.sync.aligned.m8n8.x4.shared.b16 {%0,%1,%2,%3}, [%4];"
                 : "=r"(r[0]), "=r"(r[1]), "=r"(r[2]), "=r"(r[3]) : "r"(addr));
}

// ---------------- prep: split H (and W transposed) into bf16 hi/lo words ----------------
__global__ void k_prep(const float* __restrict__ H, const float* __restrict__ W) {
    int i = blockIdx.x * blockDim.x + threadIdx.x;
    if (i < NN * 64) {
        float2 v = *(const float2*)&H[i * 2];
        unsigned hi, lo;
        pack_hl(v.x, v.y, hi, lo);
        g_hh[i] = hi;
        g_hl[i] = lo;
    } else if (i < NN * 64 + 128 * 64) {
        int w = i - NN * 64;
        int col = w >> 6;
        int kp = w & 63;
        float x0 = W[(2 * kp) * 128 + col];
        float x1 = W[(2 * kp + 1) * 128 + col];
        unsigned hi, lo;
        pack_hl(x0, x1, hi, lo);
        g_wh[w] = hi;
        g_wl[w] = lo;
    }
}

// ---------------- kernel 1: bf16x3 tensor GEMM + fused attn dots (LDSM fragments) ----------------
#define NKP 12
__global__ __launch_bounds__(256) void k_gemm_bf(const float* __restrict__ Bv,
                                                 const float* __restrict__ AW) {
    __shared__ __align__(16) unsigned Ah[128 * NKP], Al[128 * NKP];
    __shared__ __align__(16) unsigned Bh[128 * NKP], Bl[128 * NKP];
    __shared__ float s_sp[128][2], s_tp[128][2];

    const int tid = threadIdx.x;
    const int lane = tid & 31;
    const int wid = tid >> 5;
    const int g = lane >> 2;
    const int t = lane & 3;
    const int wr = wid & 3;
    const int wc = wid >> 2;
    const int row0 = blockIdx.x * 128;

    const unsigned saAh = (unsigned)__cvta_generic_to_shared(&Ah[0]);
    const unsigned saAl = (unsigned)__cvta_generic_to_shared(&Al[0]);
    const unsigned saBh = (unsigned)__cvta_generic_to_shared(&Bh[0]);
    const unsigned saBl = (unsigned)__cvta_generic_to_shared(&Bl[0]);

    const int rselA = lane & 15;
    const int hselA = lane >> 4;
    const int cselB = (lane & 7) + ((lane >> 4) * 8);
    const int khB = (lane >> 3) & 1;

    float c[2][8][4];
#pragma unroll
    for (int mt = 0; mt < 2; mt++)
#pragma unroll
        for (int nt = 0; nt < 8; nt++)
#pragma unroll
            for (int i = 0; i < 4; i++) c[mt][nt][i] = 0.0f;

    for (int kc = 0; kc < 64; kc += 8) {
        __syncthreads();
#pragma unroll
        for (int l = 0; l < 4; l++) {
            int i = tid + l * 256;
            int row = i >> 3;
            int kp = i & 7;
            int gr = row0 + row;
            unsigned hv = 0, lv = 0;
            if (gr < NN) {
                hv = g_hh[gr * 64 + kc + kp];
                lv = g_hl[gr * 64 + kc + kp];
            }
            Ah[row * NKP + kp] = hv;
            Al[row * NKP + kp] = lv;
        }
#pragma unroll
        for (int l = 0; l < 4; l++) {
            int i = tid + l * 256;
            int col = i >> 3;
            int kp = i & 7;
            Bh[col * NKP + kp] = g_wh[col * 64 + kc + kp];
            Bl[col * NKP + kp] = g_wl[col * 64 + kc + kp];
        }
        __syncthreads();

        unsigned ah[2][4], alr[2][4];
#pragma unroll
        for (int mt = 0; mt < 2; mt++) {
            unsigned off = ((unsigned)((wr * 32 + mt * 16 + rselA) * NKP + hselA * 4)) * 4u;
            ldsm4(ah[mt], saAh + off);
            ldsm4(alr[mt], saAl + off);
        }
#pragma unroll
        for (int ntp = 0; ntp < 4; ntp++) {
            unsigned boff = ((unsigned)((wc * 64 + ntp * 16 + cselB) * NKP + khB * 4)) * 4u;
            unsigned bh4[4], bl4[4];
            ldsm4(bh4, saBh + boff);
            ldsm4(bl4, saBl + boff);
#pragma unroll
            for (int sub = 0; sub < 2; sub++) {
                int nt = ntp * 2 + sub;
                unsigned b0h = bh4[sub * 2], b1h = bh4[sub * 2 + 1];
                unsigned b0l = bl4[sub * 2], b1l = bl4[sub * 2 + 1];
#pragma unroll
                for (int mt = 0; mt < 2; mt++) {
                    mma_bf16(c[mt][nt], ah[mt], b0h, b1h);    // hi*hi
                    mma_bf16(c[mt][nt], alr[mt], b0h, b1h);   // lo*hi
                    mma_bf16(c[mt][nt], ah[mt], b0l, b1l);    // hi*lo
                }
            }
        }
    }

    // epilogue: bias + clamp + store z + fused attention dots
    float sp0[2] = {0.f, 0.f}, tp0[2] = {0.f, 0.f};
    float sp1[2] = {0.f, 0.f}, tp1[2] = {0.f, 0.f};
#pragma unroll
    for (int mt = 0; mt < 2; mt++) {
        int rl0 = wr * 32 + mt * 16 + g;
        int gr0 = row0 + rl0, gr1 = gr0 + 8;
#pragma unroll
        for (int nt = 0; nt < 8; nt++) {
            int col = wc * 64 + nt * 8 + t * 2;
            float2 bb = *(const float2*)&Bv[col];
            float2 ws2 = *(const float2*)&AW[col];
            float2 wd2 = *(const float2*)&AW[128 + col];
            float v0 = clamp_inf(c[mt][nt][0] + bb.x);
            float v1 = clamp_inf(c[mt][nt][1] + bb.y);
            float v2 = clamp_inf(c[mt][nt][2] + bb.x);
            float v3 = clamp_inf(c[mt][nt][3] + bb.y);
            if (gr0 < NN) *(float2*)&g_z[gr0 * 128 + col] = make_float2(v0, v1);
            if (gr1 < NN) *(float2*)&g_z[gr1 * 128 + col] = make_float2(v2, v3);
            sp0[mt] += v0 * ws2.x + v1 * ws2.y;
            tp0[mt] += v0 * wd2.x + v1 * wd2.y;
            sp1[mt] += v2 * ws2.x + v3 * ws2.y;
            tp1[mt] += v2 * wd2.x + v3 * wd2.y;
        }
    }
#pragma unroll
    for (int o = 1; o <= 2; o <<= 1) {
#pragma unroll
        for (int mt = 0; mt < 2; mt++) {
            sp0[mt] += __shfl_xor_sync(0xffffffffu, sp0[mt], o);
            tp0[mt] += __shfl_xor_sync(0xffffffffu, tp0[mt], o);
            sp1[mt] += __shfl_xor_sync(0xffffffffu, sp1[mt], o);
            tp1[mt] += __shfl_xor_sync(0xffffffffu, tp1[mt], o);
        }
    }
    if (t == 0) {
#pragma unroll
        for (int mt = 0; mt < 2; mt++) {
            int rl = wr * 32 + mt * 16 + g;
            s_sp[rl][wc] = sp0[mt];      s_tp[rl][wc] = tp0[mt];
            s_sp[rl + 8][wc] = sp1[mt];  s_tp[rl + 8][wc] = tp1[mt];
        }
    }
    __syncthreads();
    if (tid < 128) {
        int gr = row0 + tid;
        if (gr < NN) {
            g_s[gr] = s_sp[tid][0] + s_sp[tid][1];
            g_t[gr] = s_tp[tid][0] + s_tp[tid][1];
        }
    }
}

// ---------------- kernel 2: degree histogram (4 edges/thread) ----------------
__global__ void k_hist(const int* __restrict__ dst) {
    int i = (blockIdx.x * blockDim.x + threadIdx.x) * 4;
    if (i >= NE) return;
    int4 d4 = *(const int4*)&dst[i];
    atomicAdd(&g_cnt[d4.x], 1);
    atomicAdd(&g_cnt[d4.y], 1);
    atomicAdd(&g_cnt[d4.z], 1);
    atomicAdd(&g_cnt[d4.w], 1);
}

// ---------------- kernel 3: exclusive scan (single block) ----------------
__global__ __launch_bounds__(1024) void k_scan() {
    __shared__ int sums[1024];
    const int t = threadIdx.x;
    const int C = (NN + 1023) / 1024;
    int b = t * C;
    int e = min(b + C, NN);
    int s = 0;
    for (int i = b; i < e; i++) s += g_cnt[i];
    sums[t] = s;
    __syncthreads();
    for (int off = 1; off < 1024; off <<= 1) {
        int v = (t >= off) ? sums[t - off] : 0;
        __syncthreads();
        sums[t] += v;
        __syncthreads();
    }
    int running = sums[t] - s;
    for (int i = b; i < e; i++) {
        g_off[i] = running;
        g_cursor[i] = running;
        running += g_cnt[i];
    }
    if (t == 1023) g_off[NN] = NE;
}

// ---------------- kernel 4: thin CSR fill + re-zero counters for next replay ----------------
__global__ void k_fill(const int* __restrict__ src, const int* __restrict__ dst,
                       const float* __restrict__ sigma) {
    int gt = blockIdx.x * blockDim.x + threadIdx.x;
    int i = gt * 4;
    if (i < NE) {
        int4 s4 = *(const int4*)&src[i];
        int4 d4 = *(const int4*)&dst[i];
        float4 g4 = *(const float4*)&sigma[i];
        int p;
        p = atomicAdd(&g_cursor[d4.x], 1); g_pack[p] = make_int2(s4.x, __float_as_int(g4.x));
        p = atomicAdd(&g_cursor[d4.y], 1); g_pack[p] = make_int2(s4.y, __float_as_int(g4.y));
        p = atomicAdd(&g_cursor[d4.z], 1); g_pack[p] = make_int2(s4.z, __float_as_int(g4.z));
        p = atomicAdd(&g_cursor[d4.w], 1); g_pack[p] = make_int2(s4.w, __float_as_int(g4.w));
    }
    if (gt < NN) g_cnt[gt] = 0;                          // for next replay
    if (gt < DD) { g_colsum[gt] = 0.0f; g_colsq[gt] = 0.0f; }
}

// ---------------- kernel 5: online softmax, rescale amortized per 8 edges ----------------
// one warp per node, 8 warps per block; scalar batch of 8 edges -> one rescale ->
// two 4-wide gather sub-batches (z loads stay 4 in flight).
__global__ __launch_bounds__(256) void k_node(const float* __restrict__ attnb) {
    __shared__ float s_sum[DD];
    __shared__ float s_sq[DD];
    const int tid = threadIdx.x;
    if (tid < DD) { s_sum[tid] = 0.0f; s_sq[tid] = 0.0f; }
    __syncthreads();

    const int lane = tid & 31;
    const int node = blockIdx.x * 8 + (tid >> 5);   // NN = 6250*8 exactly

    const int beg = g_off[node];
    const int end = g_off[node + 1];
    const float tb = g_t[node] + attnb[0];
    const int co = lane * 4;

    float m = -FLT_MAX, den = 0.0f, bsum = 0.0f;
    float4 a0 = make_float4(0.f, 0.f, 0.f, 0.f);
    float4 a1 = make_float4(0.f, 0.f, 0.f, 0.f);
    float4 a2 = make_float4(0.f, 0.f, 0.f, 0.f);
    float4 a3 = make_float4(0.f, 0.f, 0.f, 0.f);

    int j = beg;
    // main loop: 8 edges per iteration, single rescale
    for (; j + 7 < end; j += 8) {
        int2 p0 = g_pack[j],     p1 = g_pack[j + 1];
        int2 p2 = g_pack[j + 2], p3 = g_pack[j + 3];
        int2 p4 = g_pack[j + 4], p5 = g_pack[j + 5];
        int2 p6 = g_pack[j + 6], p7 = g_pack[j + 7];
        float aa;
        float e0, e1, e2, e3, e4, e5, e6, e7;
        aa = clamp_inf(g_s[p0.x] + tb); e0 = (aa > 0.f) ? aa : 0.01f * aa;
        aa = clamp_inf(g_s[p1.x] + tb); e1 = (aa > 0.f) ? aa : 0.01f * aa;
        aa = clamp_inf(g_s[p2.x] + tb); e2 = (aa > 0.f) ? aa : 0.01f * aa;
        aa = clamp_inf(g_s[p3.x] + tb); e3 = (aa > 0.f) ? aa : 0.01f * aa;
        aa = clamp_inf(g_s[p4.x] + tb); e4 = (aa > 0.f) ? aa : 0.01f * aa;
        aa = clamp_inf(g_s[p5.x] + tb); e5 = (aa > 0.f) ? aa : 0.01f * aa;
        aa = clamp_inf(g_s[p6.x] + tb); e6 = (aa > 0.f) ? aa : 0.01f * aa;
        aa = clamp_inf(g_s[p7.x] + tb); e7 = (aa > 0.f) ? aa : 0.01f * aa;
        float l8 = fmaxf(fmaxf(fmaxf(e0, e1), fmaxf(e2, e3)),
                         fmaxf(fmaxf(e4, e5), fmaxf(e6, e7)));
        float mn = fmaxf(m, l8);
        float f = __expf(m - mn);
        m = mn;
        den *= f;
        a0.x *= f; a0.y *= f; a0.z *= f; a0.w *= f;
        a1.x *= f; a1.y *= f; a1.z *= f; a1.w *= f;
        a2.x *= f; a2.y *= f; a2.z *= f; a2.w *= f;
        a3.x *= f; a3.y *= f; a3.z *= f; a3.w *= f;
        float w0 = __expf(e0 - m), w1 = __expf(e1 - m);
        float w2 = __expf(e2 - m), w3 = __expf(e3 - m);
        float w4 = __expf(e4 - m), w5 = __expf(e5 - m);
        float w6 = __expf(e6 - m), w7 = __expf(e7 - m);
        den += ((w0 + w1) + (w2 + w3)) + ((w4 + w5) + (w6 + w7));
        float s0 = __int_as_float(p0.y), s1 = __int_as_float(p1.y);
        float s2 = __int_as_float(p2.y), s3 = __int_as_float(p3.y);
        float s4 = __int_as_float(p4.y), s5 = __int_as_float(p5.y);
        float s6 = __int_as_float(p6.y), s7 = __int_as_float(p7.y);
        bsum += ((s0 + s1) + (s2 + s3)) + ((s4 + s5) + (s6 + s7));
        // gather sub-batch A (4 z-loads in flight)
        {
            float4 z0 = *(const float4*)&g_z[p0.x * DD + co];
            float4 z1 = *(const float4*)&g_z[p1.x * DD + co];
            float4 z2 = *(const float4*)&g_z[p2.x * DD + co];
            float4 z3 = *(const float4*)&g_z[p3.x * DD + co];
            float c0 = w0 * s0, c1 = w1 * s1, c2 = w2 * s2, c3 = w3 * s3;
            a0.x += c0 * z0.x; a0.y += c0 * z0.y; a0.z += c0 * z0.z; a0.w += c0 * z0.w;
            a1.x += c1 * z1.x; a1.y += c1 * z1.y; a1.z += c1 * z1.z; a1.w += c1 * z1.w;
            a2.x += c2 * z2.x; a2.y += c2 * z2.y; a2.z += c2 * z2.z; a2.w += c2 * z2.w;
            a3.x += c3 * z3.x; a3.y += c3 * z3.y; a3.z += c3 * z3.z; a3.w += c3 * z3.w;
        }
        // gather sub-batch B
        {
            float4 z4 = *(const float4*)&g_z[p4.x * DD + co];
            float4 z5 = *(const float4*)&g_z[p5.x * DD + co];
            float4 z6 = *(const float4*)&g_z[p6.x * DD + co];
            float4 z7 = *(const float4*)&g_z[p7.x * DD + co];
            float c4 = w4 * s4, c5 = w5 * s5, c6 = w6 * s6, c7 = w7 * s7;
            a0.x += c4 * z4.x; a0.y += c4 * z4.y; a0.z += c4 * z4.z; a0.w += c4 * z4.w;
            a1.x += c5 * z5.x; a1.y += c5 * z5.y; a1.z += c5 * z5.z; a1.w += c5 * z5.w;
            a2.x += c6 * z6.x; a2.y += c6 * z6.y; a2.z += c6 * z6.z; a2.w += c6 * z6.w;
            a3.x += c7 * z7.x; a3.y += c7 * z7.y; a3.z += c7 * z7.z; a3.w += c7 * z7.w;
        }
    }
    // middle: 4-edge batch
    for (; j + 3 < end; j += 4) {
        int2 p0 = g_pack[j],     p1 = g_pack[j + 1];
        int2 p2 = g_pack[j + 2], p3 = g_pack[j + 3];
        float4 z0 = *(const float4*)&g_z[p0.x * DD + co];
        float4 z1 = *(const float4*)&g_z[p1.x * DD + co];
        float4 z2 = *(const float4*)&g_z[p2.x * DD + co];
        float4 z3 = *(const float4*)&g_z[p3.x * DD + co];
        float aa, e0, e1, e2, e3;
        aa = clamp_inf(g_s[p0.x] + tb); e0 = (aa > 0.f) ? aa : 0.01f * aa;
        aa = clamp_inf(g_s[p1.x] + tb); e1 = (aa > 0.f) ? aa : 0.01f * aa;
        aa = clamp_inf(g_s[p2.x] + tb); e2 = (aa > 0.f) ? aa : 0.01f * aa;
        aa = clamp_inf(g_s[p3.x] + tb); e3 = (aa > 0.f) ? aa : 0.01f * aa;
        float l4 = fmaxf(fmaxf(e0, e1), fmaxf(e2, e3));
        float mn = fmaxf(m, l4);
        float f = __expf(m - mn);
        m = mn;
        den *= f;
        a0.x *= f; a0.y *= f; a0.z *= f; a0.w *= f;
        a1.x *= f; a1.y *= f; a1.z *= f; a1.w *= f;
        a2.x *= f; a2.y *= f; a2.z *= f; a2.w *= f;
        a3.x *= f; a3.y *= f; a3.z *= f; a3.w *= f;
        float w0 = __expf(e0 - m), w1 = __expf(e1 - m);
        float w2 = __expf(e2 - m), w3 = __expf(e3 - m);
        den += (w0 + w1) + (w2 + w3);
        float s0 = __int_as_float(p0.y), s1 = __int_as_float(p1.y);
        float s2 = __int_as_float(p2.y), s3 = __int_as_float(p3.y);
        bsum += (s0 + s1) + (s2 + s3);
        float c0 = w0 * s0, c1 = w1 * s1, c2 = w2 * s2, c3 = w3 * s3;
        a0.x += c0 * z0.x; a0.y += c0 * z0.y; a0.z += c0 * z0.z; a0.w += c0 * z0.w;
        a1.x += c1 * z1.x; a1.y += c1 * z1.y; a1.z += c1 * z1.z; a1.w += c1 * z1.w;
        a2.x += c2 * z2.x; a2.y += c2 * z2.y; a2.z += c2 * z2.z; a2.w += c2 * z2.w;
        a3.x += c3 * z3.x; a3.y += c3 * z3.y; a3.z += c3 * z3.z; a3.w += c3 * z3.w;
    }
    // tail: single edges
    for (; j < end; j++) {
        int2 p0 = g_pack[j];
        float4 z0 = *(const float4*)&g_z[p0.x * DD + co];
        float aa = clamp_inf(g_s[p0.x] + tb);
        float e0 = (aa > 0.f) ? aa : 0.01f * aa;
        float mn = fmaxf(m, e0);
        float f = __expf(m - mn);
        m = mn;
        den *= f;
        a0.x *= f; a0.y *= f; a0.z *= f; a0.w *= f;
        a1.x *= f; a1.y *= f; a1.z *= f; a1.w *= f;
        a2.x *= f; a2.y *= f; a2.z *= f; a2.w *= f;
        a3.x *= f; a3.y *= f; a3.z *= f; a3.w *= f;
        float w0 = __expf(e0 - m);
        den += w0;
        float s0 = __int_as_float(p0.y);
        bsum += s0;
        float c0 = w0 * s0;
        a0.x += c0 * z0.x; a0.y += c0 * z0.y; a0.z += c0 * z0.z; a0.w += c0 * z0.w;
    }

    float rc = (den > 0.0f) ? (1.0f / den) * (1.0f / (bsum + 1e-6f)) : 0.0f;
    float4 v;
    v.x = clamp_inf(((a0.x + a1.x) + (a2.x + a3.x)) * rc);
    v.y = clamp_inf(((a0.y + a1.y) + (a2.y + a3.y)) * rc);
    v.z = clamp_inf(((a0.z + a1.z) + (a2.z + a3.z)) * rc);
    v.w = clamp_inf(((a0.w + a1.w) + (a2.w + a3.w)) * rc);
    *(float4*)&g_hnew[node * DD + co] = v;

    atomicAdd(&s_sum[co + 0], v.x); atomicAdd(&s_sq[co + 0], v.x * v.x);
    atomicAdd(&s_sum[co + 1], v.y); atomicAdd(&s_sq[co + 1], v.y * v.y);
    atomicAdd(&s_sum[co + 2], v.z); atomicAdd(&s_sq[co + 2], v.z * v.z);
    atomicAdd(&s_sum[co + 3], v.w); atomicAdd(&s_sq[co + 3], v.w * v.w);

    __syncthreads();
    if (tid < DD) {
        atomicAdd(&g_colsum[tid], s_sum[tid]);
        atomicAdd(&g_colsq[tid], s_sq[tid]);
    }
}

// ---------------- kernel 6: batchnorm + elu (vectorized) ----------------
__global__ void k_bn(float* __restrict__ out, const float* __restrict__ gamma,
                     const float* __restrict__ beta) {
    int i = blockIdx.x * blockDim.x + threadIdx.x;   // float4 index
    if (i >= NN * DD / 4) return;
    int c = (i & 31) * 4;
    const float inv_n = 1.0f / (float)NN;
    float4 cs = *(float4*)&g_colsum[c];
    float4 cq = *(float4*)&g_colsq[c];
    float4 gm = *(const float4*)&gamma[c];
    float4 bt = *(const float4*)&beta[c];
    float4 hv = *(float4*)&g_hnew[i * 4];
    float mu, var, xb;
    float4 o;
    mu = cs.x * inv_n; var = cq.x * inv_n - mu * mu;
    xb = (hv.x - mu) * rsqrtf(var + 1e-5f) * gm.x + bt.x;
    o.x = (xb > 0.0f) ? xb : expm1f(xb);
    mu = cs.y * inv_n; var = cq.y * inv_n - mu * mu;
    xb = (hv.y - mu) * rsqrtf(var + 1e-5f) * gm.y + bt.y;
    o.y = (xb > 0.0f) ? xb : expm1f(xb);
    mu = cs.z * inv_n; var = cq.z * inv_n - mu * mu;
    xb = (hv.z - mu) * rsqrtf(var + 1e-5f) * gm.z + bt.z;
    o.z = (xb > 0.0f) ? xb : expm1f(xb);
    mu = cs.w * inv_n; var = cq.w * inv_n - mu * mu;
    xb = (hv.w - mu) * rsqrtf(var + 1e-5f) * gm.w + bt.w;
    o.w = (xb > 0.0f) ? xb : expm1f(xb);
    *(float4*)&out[i * 4] = o;
}

// ---------------- launcher (exact R9 structure: blocking side stream) ----------------
extern "C" void kernel_launch(void* const* d_in, const int* in_sizes, int n_in,
                              void* d_out, int out_size) {
    const float* h     = (const float*)d_in[0];
    const int*   src   = (const int*)d_in[1];
    const int*   dst   = (const int*)d_in[2];
    const float* sigma = (const float*)d_in[3];
    const float* fcw   = (const float*)d_in[4];
    const float* fcb   = (const float*)d_in[5];
    const float* attnw = (const float*)d_in[6];
    const float* attnb = (const float*)d_in[7];
    const float* gamma = (const float*)d_in[8];
    const float* beta  = (const float*)d_in[9];
    float* out = (float*)d_out;

    static cudaStream_t s2 = nullptr;
    static cudaEvent_t ev_fork = nullptr, ev_join = nullptr;
    if (s2 == nullptr) {
        cudaStreamCreate(&s2);
        cudaEventCreateWithFlags(&ev_fork, cudaEventDisableTiming);
        cudaEventCreateWithFlags(&ev_join, cudaEventDisableTiming);
    }

    cudaEventRecord(ev_fork, 0);
    cudaStreamWaitEvent(s2, ev_fork, 0);
    k_hist<<<(NE / 4 + 255) / 256, 256, 0, s2>>>(dst);
    k_scan<<<1, 1024, 0, s2>>>();
    k_fill<<<(NE / 4 + 255) / 256, 256, 0, s2>>>(src, dst, sigma);
    cudaEventRecord(ev_join, s2);

    k_prep<<<(NN * 64 + 128 * 64 + 255) / 256, 256>>>(h, fcw);
    k_gemm_bf<<<(NN + 127) / 128, 256>>>(fcb, attnw);

    cudaStreamWaitEvent(0, ev_join, 0);
    k_node<<<NN / 8, 256>>>(attnb);
    k_bn<<<(NN * DD / 4 + 255) / 256, 256>>>(out, gamma, beta);
}